// round 11
// baseline (speedup 1.0000x reference)
#include <cuda_runtime.h>
#include <cuda_fp16.h>
#include <math.h>
#include <stdint.h>

// B=2048 windows, N=49, C=384, H=12, hd=32, nW=64
__device__ float g_q  [2048u*12*49*32];
__device__ float g_k  [2048u*12*49*32];
__device__ float g_v  [2048u*12*49*32];
__device__ __half g_oh[2048u*49*384];   // attn out hi (fp16)
__device__ __half g_ol[2048u*49*384];   // attn out lo (fp16, x2048)
__device__ __half g_xh[2048u*49*384];
__device__ __half g_xl[2048u*49*384];
__device__ __half g_wh[1152*384];
__device__ __half g_wl[1152*384];
__device__ __half g_ph[384*384];
__device__ __half g_pl[384*384];
__device__ float g_bt [169*12];
__device__ float g_rpb[12*49*49];

#define LO_SCALE 2048.f
#define LO_INV   (1.f / 2048.f)

// ---------------------------------------------------------------------------
__device__ __forceinline__ uint32_t smem_u32(const void* p) {
    uint32_t a;
    asm("{ .reg .u64 t; cvta.to.shared.u64 t, %1; cvt.u32.u64 %0, t; }" : "=r"(a) : "l"(p));
    return a;
}
__device__ __forceinline__ void cp_async16(uint32_t dst, const void* src) {
    asm volatile("cp.async.cg.shared.global [%0], [%1], 16;" :: "r"(dst), "l"(src));
}
#define CP_COMMIT() asm volatile("cp.async.commit_group;" ::: "memory")
template<int N> __device__ __forceinline__ void cp_wait() {
    asm volatile("cp.async.wait_group %0;" :: "n"(N) : "memory");
}
__device__ __forceinline__ void ldsm4(uint32_t& r0, uint32_t& r1, uint32_t& r2, uint32_t& r3,
                                      uint32_t addr) {
    asm volatile("ldmatrix.sync.aligned.m8n8.x4.shared.b16 {%0,%1,%2,%3}, [%4];"
                 : "=r"(r0), "=r"(r1), "=r"(r2), "=r"(r3) : "r"(addr));
}
__device__ __forceinline__ void mma_f16(float& c0, float& c1, float& c2, float& c3,
                                        uint32_t a0, uint32_t a1, uint32_t a2, uint32_t a3,
                                        uint32_t b0, uint32_t b1) {
    asm volatile("mma.sync.aligned.m16n8k16.row.col.f32.f16.f16.f32 "
                 "{%0,%1,%2,%3}, {%4,%5,%6,%7}, {%8,%9}, {%0,%1,%2,%3};"
                 : "+f"(c0), "+f"(c1), "+f"(c2), "+f"(c3)
                 : "r"(a0), "r"(a1), "r"(a2), "r"(a3), "r"(b0), "r"(b1));
}
// fp16-accumulate variant: c0 = {row g: col2t, col2t+1}, c1 = {row g+8: ...}
__device__ __forceinline__ void mma_f16acc(uint32_t& c0, uint32_t& c1,
                                           uint32_t a0, uint32_t a1, uint32_t a2, uint32_t a3,
                                           uint32_t b0, uint32_t b1) {
    asm volatile("mma.sync.aligned.m16n8k16.row.col.f16.f16.f16.f16 "
                 "{%0,%1}, {%2,%3,%4,%5}, {%6,%7}, {%0,%1};"
                 : "+r"(c0), "+r"(c1)
                 : "r"(a0), "r"(a1), "r"(a2), "r"(a3), "r"(b0), "r"(b1));
}

// ---------------------------------------------------------------------------
// fp16 hi/lo split: hi = f16(x), lo = f16((x - hi) * 2048)
// ---------------------------------------------------------------------------
__global__ void splith_kernel(const float* __restrict__ in, __half* __restrict__ hi,
                              __half* __restrict__ lo, int n4) {
    int i = blockIdx.x * 256 + threadIdx.x;
    if (i >= n4) return;
    float4 v = ((const float4*)in)[i];
    float vv[4] = {v.x, v.y, v.z, v.w};
    __half h[4], l[4];
    #pragma unroll
    for (int j = 0; j < 4; j++) {
        h[j] = __float2half_rn(vv[j]);
        l[j] = __float2half_rn((vv[j] - __half2float(h[j])) * LO_SCALE);
    }
    ((__half2*)hi)[2*i]   = __half2{h[0], h[1]};
    ((__half2*)hi)[2*i+1] = __half2{h[2], h[3]};
    ((__half2*)lo)[2*i]   = __half2{l[0], l[1]};
    ((__half2*)lo)[2*i+1] = __half2{l[2], l[3]};
}

// ---------------------------------------------------------------------------
// CPB MLP + gather
// ---------------------------------------------------------------------------
__global__ void cpb_kernel(const float* __restrict__ table, const float* __restrict__ w1,
                           const float* __restrict__ b1, const float* __restrict__ w2) {
    __shared__ float red[16];
    int t = blockIdx.x, j = threadIdx.x;
    float t0 = table[t * 2 + 0], t1 = table[t * 2 + 1];
    float h = fmaxf(fmaf(t0, w1[j * 2 + 0], fmaf(t1, w1[j * 2 + 1], b1[j])), 0.f);
    for (int hh = 0; hh < 12; hh++) {
        float v = h * w2[hh * 512 + j];
        #pragma unroll
        for (int o = 16; o > 0; o >>= 1) v += __shfl_down_sync(0xffffffffu, v, o);
        if ((j & 31) == 0) red[j >> 5] = v;
        __syncthreads();
        if (j == 0) {
            float s = 0.f;
            #pragma unroll
            for (int w = 0; w < 16; w++) s += red[w];
            g_bt[t * 12 + hh] = 16.f / (1.f + expf(-s));
        }
        __syncthreads();
    }
}
__global__ void gather_kernel(const int* __restrict__ idx) {
    int e = blockIdx.x * 256 + threadIdx.x;
    if (e >= 12 * 49 * 49) return;
    int h = e / 2401, ij = e - h * 2401;
    g_rpb[e] = g_bt[idx[ij] * 12 + h];
}

// ---------------------------------------------------------------------------
// fp16-limb warp-MMA GEMM, K-chunk 64, 2-stage cp.async, pitch-72 rows.
// Main term (hi*hi): fp32 accum. Cross terms: fp16 accum (2x rate if supported).
// TERMS=3: + (lo*hi + hi*lo)/2048 (q,k). TERMS=2: drops hi*lo (v, proj).
// 512 thr, 16 warps 4x4, warp tile 32x32, 128x128 block tile.
// ---------------------------------------------------------------------------
#define PITCHE 72                         // fp16 elems per smem row (144B)
#define COMP_B (128 * PITCHE * 2)         // 18432 B per limb tile
#define STAGE_B (4 * COMP_B)              // 73728
#define GEMM_SMEM (2 * STAGE_B)           // 147456

template<int TERMS>
__global__ void __launch_bounds__(512) gemm_mma(
    const __half* __restrict__ Ahi, const __half* __restrict__ Alo,
    const __half* __restrict__ Bhi, const __half* __restrict__ Blo,
    int mode, int n_base,
    const float* __restrict__ bq, const float* __restrict__ bv,
    const float* __restrict__ bp, float* __restrict__ outp)
{
    extern __shared__ char sm[];
    uint32_t sbase = smem_u32(sm);
    int tid = threadIdx.x, wid = tid >> 5, lane = tid & 31;
    int g = lane >> 2, t = lane & 3;
    int grp = lane >> 3, rin = lane & 7;
    int m0 = blockIdx.x * 128, n0 = n_base + blockIdx.y * 128;
    int wm = (wid >> 2) * 32, wn = (wid & 3) * 32;

    float cm[2][4][4];
    uint32_t cxp[2][4][2];               // packed half2 accumulators
    #pragma unroll
    for (int mi = 0; mi < 2; mi++)
        #pragma unroll
        for (int nj = 0; nj < 4; nj++) {
            #pragma unroll
            for (int r = 0; r < 4; r++) cm[mi][nj][r] = 0.f;
            cxp[mi][nj][0] = 0u; cxp[mi][nj][1] = 0u;
        }

    // ldmatrix byte offsets within a [128][PITCHE] fp16 tile
    uint32_t abyte[2], bbyte[2];
    #pragma unroll
    for (int mi = 0; mi < 2; mi++)
        abyte[mi] = (uint32_t)((wm + 16 * mi + (grp & 1) * 8 + rin) * (PITCHE * 2)
                               + (grp >> 1) * 16);
    #pragma unroll
    for (int j = 0; j < 2; j++)
        bbyte[j] = (uint32_t)((wn + 16 * j + (grp >> 1) * 8 + rin) * (PITCHE * 2)
                              + (grp & 1) * 16);

    // stage loader: 128 rows x 64 k fp16 per limb
    auto load_stage = [&](int it, int s) {
        int k0 = it * 64;
        uint32_t sb = sbase + s * STAGE_B;
        #pragma unroll
        for (int q = 0; q < 2; q++) {
            int cc = q * 512 + tid;
            int r = cc >> 3, seg = cc & 7;
            uint32_t off = (uint32_t)(r * (PITCHE * 2) + seg * 16);
            size_t ga = (size_t)(m0 + r) * 384 + k0 + seg * 8;
            size_t gb = (size_t)(n0 + r) * 384 + k0 + seg * 8;
            cp_async16(sb + 0 * COMP_B + off, Ahi + ga);
            cp_async16(sb + 1 * COMP_B + off, Alo + ga);
            cp_async16(sb + 2 * COMP_B + off, Bhi + gb);
            if (TERMS == 3) cp_async16(sb + 3 * COMP_B + off, Blo + gb);
        }
        CP_COMMIT();
    };

    load_stage(0, 0);
    load_stage(1, 1);

    for (int it = 0; it < 6; ++it) {
        int s = it & 1;
        if (it < 5) cp_wait<1>(); else cp_wait<0>();
        __syncthreads();
        uint32_t sb = sbase + s * STAGE_B;
        #pragma unroll
        for (int kc = 0; kc < 4; kc++) {
            uint32_t kb = (uint32_t)(kc * 32);  // 16 fp16 = 32 bytes per k16
            uint32_t ah[2][4], al[2][4], bh[2][4], bl[2][4];
            #pragma unroll
            for (int mi = 0; mi < 2; mi++) {
                uint32_t ao = sb + abyte[mi] + kb;
                ldsm4(ah[mi][0], ah[mi][1], ah[mi][2], ah[mi][3], ao + 0 * COMP_B);
                ldsm4(al[mi][0], al[mi][1], al[mi][2], al[mi][3], ao + 1 * COMP_B);
            }
            #pragma unroll
            for (int j = 0; j < 2; j++) {
                uint32_t bo = sb + bbyte[j] + kb;
                ldsm4(bh[j][0], bh[j][1], bh[j][2], bh[j][3], bo + 2 * COMP_B);
                if (TERMS == 3)
                    ldsm4(bl[j][0], bl[j][1], bl[j][2], bl[j][3], bo + 3 * COMP_B);
            }
            // main term, fp32 accum
            #pragma unroll
            for (int mi = 0; mi < 2; mi++)
                #pragma unroll
                for (int nj = 0; nj < 4; nj++) {
                    int j = nj >> 1, hf = (nj & 1) * 2;
                    mma_f16(cm[mi][nj][0], cm[mi][nj][1], cm[mi][nj][2], cm[mi][nj][3],
                            ah[mi][0], ah[mi][1], ah[mi][2], ah[mi][3],
                            bh[j][hf], bh[j][hf + 1]);
                }
            // cross terms, fp16 accum
            #pragma unroll
            for (int mi = 0; mi < 2; mi++)
                #pragma unroll
                for (int nj = 0; nj < 4; nj++) {
                    int j = nj >> 1, hf = (nj & 1) * 2;
                    mma_f16acc(cxp[mi][nj][0], cxp[mi][nj][1],
                               al[mi][0], al[mi][1], al[mi][2], al[mi][3],
                               bh[j][hf], bh[j][hf + 1]);
                }
            if (TERMS == 3) {
                #pragma unroll
                for (int mi = 0; mi < 2; mi++)
                    #pragma unroll
                    for (int nj = 0; nj < 4; nj++) {
                        int j = nj >> 1, hf = (nj & 1) * 2;
                        mma_f16acc(cxp[mi][nj][0], cxp[mi][nj][1],
                                   ah[mi][0], ah[mi][1], ah[mi][2], ah[mi][3],
                                   bl[j][hf], bl[j][hf + 1]);
                    }
            }
        }
        __syncthreads();
        if (it + 2 < 6) load_stage(it + 2, s);
    }

    #pragma unroll
    for (int mi = 0; mi < 2; mi++) {
        #pragma unroll
        for (int half = 0; half < 2; half++) {
            int row = m0 + wm + 16 * mi + g + 8 * half;
            int b = row / 49, nn = row - b * 49;
            #pragma unroll
            for (int nj = 0; nj < 4; nj++) {
                int col = n0 + wn + 8 * nj + 2 * t;
                __half2 cxh = *(__half2*)&cxp[mi][nj][half];
                float2 v;
                v.x = fmaf(__low2float(cxh),  LO_INV, cm[mi][nj][2 * half + 0]);
                v.y = fmaf(__high2float(cxh), LO_INV, cm[mi][nj][2 * half + 1]);
                if (mode == 0) {
                    int which = col / 384;
                    int rem = col - which * 384;
                    int h = rem >> 5, d = rem & 31;
                    if (which == 0)      { v.x += bq[rem]; v.y += bq[rem + 1]; }
                    else if (which == 2) { v.x += bv[rem]; v.y += bv[rem + 1]; }
                    float* dst = ((which == 0) ? g_q : (which == 1) ? g_k : g_v)
                                 + (((size_t)b * 12 + h) * 49 + nn) * 32 + d;
                    *(float2*)dst = v;
                } else {
                    v.x += bp[col]; v.y += bp[col + 1];
                    *(float2*)(outp + (size_t)row * 384 + col) = v;
                }
            }
        }
    }
}

// ---------------------------------------------------------------------------
// Attention (round-6 structure); writes fp16 hi + scaled lo for proj input.
// ---------------------------------------------------------------------------
#define QP 36
#define SP 50

__global__ void __launch_bounds__(256) attn_kernel(const float* __restrict__ mask,
                                                   const float* __restrict__ logit_scale)
{
    __shared__ float sq[49 * QP];
    __shared__ float sk[49 * QP];
    __shared__ float sv[49 * QP];
    __shared__ float sS[49 * SP];
    __shared__ float sredA[245];
    __shared__ float sredB[245];
    int bh = blockIdx.x;
    int b = bh / 12, h = bh - b * 12;
    int tid = threadIdx.x;

    size_t base = (size_t)bh * 49 * 32;
    const float4* gq4 = (const float4*)(g_q + base);
    const float4* gk4 = (const float4*)(g_k + base);
    const float4* gv4 = (const float4*)(g_v + base);
    for (int u = tid; u < 392; u += 256) {
        int r = u >> 3, c4 = (u & 7) * 4;
        *(float4*)(sq + r * QP + c4) = gq4[u];
        *(float4*)(sk + r * QP + c4) = gk4[u];
        *(float4*)(sv + r * QP + c4) = gv4[u];
    }
    __syncthreads();

    if (tid < 98) {
        int r = (tid < 49) ? tid : tid - 49;
        float* s = (tid < 49) ? sq : sk;
        float ss = 0.f;
        #pragma unroll
        for (int d = 0; d < 32; d++) { float x = s[r * QP + d]; ss = fmaf(x, x, ss); }
        float inv = 1.f / fmaxf(sqrtf(ss), 1e-12f);
        if (tid < 49) inv *= expf(fminf(logit_scale[h], 4.60517018598809136804f));
        #pragma unroll
        for (int d = 0; d < 32; d++) s[r * QP + d] *= inv;
    }
    __syncthreads();

    if (tid < 125) {
        int ip = tid / 5, jg = tid - ip * 5;
        int i0 = ip * 2, i1 = i0 + 1;
        bool has1 = (i1 < 49);
        float4 qa[8], qb[8];
        #pragma unroll
        for (int u = 0; u < 8; u++) qa[u] = *(const float4*)(sq + i0 * QP + u * 4);
        if (has1) {
            #pragma unroll
            for (int u = 0; u < 8; u++) qb[u] = *(const float4*)(sq + i1 * QP + u * 4);
        }
        #pragma unroll
        for (int jj = 0; jj < 10; jj++) {
            int j = jg * 10 + jj;
            if (j >= 49) break;
            float a0 = 0.f, a1 = 0.f;
            #pragma unroll
            for (int u = 0; u < 8; u++) {
                float4 kv = *(const float4*)(sk + j * QP + u * 4);
                a0 = fmaf(qa[u].x, kv.x, a0); a0 = fmaf(qa[u].y, kv.y, a0);
                a0 = fmaf(qa[u].z, kv.z, a0); a0 = fmaf(qa[u].w, kv.w, a0);
                if (has1) {
                    a1 = fmaf(qb[u].x, kv.x, a1); a1 = fmaf(qb[u].y, kv.y, a1);
                    a1 = fmaf(qb[u].z, kv.z, a1); a1 = fmaf(qb[u].w, kv.w, a1);
                }
            }
            sS[i0 * SP + j] = a0;
            if (has1) sS[i1 * SP + j] = a1;
        }
    }
    __syncthreads();

    int si = tid / 5, sp = tid - si * 5;
    int j0 = sp * 10, j1 = min(j0 + 10, 49);
    if (tid < 245) {
        const float* rp = g_rpb + (h * 49 + si) * 49;
        const float* mp = mask + ((size_t)(b & 63) * 49 + si) * 49;
        float lmax = -1e30f;
        for (int j = j0; j < j1; j++) {
            float s = sS[si * SP + j] + rp[j] + mp[j];
            sS[si * SP + j] = s;
            lmax = fmaxf(lmax, s);
        }
        sredA[tid] = lmax;
    }
    __syncthreads();
    if (tid < 245) {
        float mx = sredA[si * 5];
        #pragma unroll
        for (int p = 1; p < 5; p++) mx = fmaxf(mx, sredA[si * 5 + p]);
        float lsum = 0.f;
        for (int j = j0; j < j1; j++) {
            float e = expf(sS[si * SP + j] - mx);
            sS[si * SP + j] = e;
            lsum += e;
        }
        sredB[tid] = lsum;
    }
    __syncthreads();
    if (tid < 245) {
        float sum = sredB[si * 5];
        #pragma unroll
        for (int p = 1; p < 5; p++) sum += sredB[si * 5 + p];
        float inv = 1.f / sum;
        for (int j = j0; j < j1; j++) sS[si * SP + j] *= inv;
    }
    __syncthreads();

    if (tid < 104) {
        int ipart = tid >> 3, dq = tid & 7;
        int r0 = ipart * 4;
        float4 acc[4] = {{0,0,0,0},{0,0,0,0},{0,0,0,0},{0,0,0,0}};
        for (int j = 0; j < 49; j++) {
            float4 v = *(const float4*)(sv + j * QP + dq * 4);
            #pragma unroll
            for (int rr = 0; rr < 4; rr++) {
                int r = r0 + rr;
                float s = (r < 49) ? sS[r * SP + j] : 0.f;
                acc[rr].x = fmaf(s, v.x, acc[rr].x);
                acc[rr].y = fmaf(s, v.y, acc[rr].y);
                acc[rr].z = fmaf(s, v.z, acc[rr].z);
                acc[rr].w = fmaf(s, v.w, acc[rr].w);
            }
        }
        #pragma unroll
        for (int rr = 0; rr < 4; rr++) {
            int r = r0 + rr;
            if (r < 49) {
                size_t oidx = ((size_t)b * 49 + r) * 384 + h * 32 + dq * 4;
                float av[4] = {acc[rr].x, acc[rr].y, acc[rr].z, acc[rr].w};
                __half hh[4], ll[4];
                #pragma unroll
                for (int e = 0; e < 4; e++) {
                    hh[e] = __float2half_rn(av[e]);
                    ll[e] = __float2half_rn((av[e] - __half2float(hh[e])) * LO_SCALE);
                }
                *(__half2*)(g_oh + oidx)     = __half2{hh[0], hh[1]};
                *(__half2*)(g_oh + oidx + 2) = __half2{hh[2], hh[3]};
                *(__half2*)(g_ol + oidx)     = __half2{ll[0], ll[1]};
                *(__half2*)(g_ol + oidx + 2) = __half2{ll[2], ll[3]};
            }
        }
    }
}

// ---------------------------------------------------------------------------
extern "C" void kernel_launch(void* const* d_in, const int* in_sizes, int n_in,
                              void* d_out, int out_size) {
    const float* x           = (const float*)d_in[0];
    const float* mask        = (const float*)d_in[1];
    const float* qkv_w       = (const float*)d_in[2];
    const float* q_bias      = (const float*)d_in[3];
    const float* v_bias      = (const float*)d_in[4];
    const float* logit_scale = (const float*)d_in[5];
    const float* cpb_w1      = (const float*)d_in[6];
    const float* cpb_b1      = (const float*)d_in[7];
    const float* cpb_w2      = (const float*)d_in[8];
    const float* proj_w      = (const float*)d_in[9];
    const float* proj_b      = (const float*)d_in[10];
    const float* table       = (const float*)d_in[11];
    const int*   idx         = (const int*)d_in[12];
    float* out = (float*)d_out;

    cudaFuncSetAttribute(gemm_mma<3>, cudaFuncAttributeMaxDynamicSharedMemorySize, GEMM_SMEM);
    cudaFuncSetAttribute(gemm_mma<2>, cudaFuncAttributeMaxDynamicSharedMemorySize, GEMM_SMEM);

    __half *xh, *xl, *wh, *wl, *ph, *pl, *oh, *ol;
    cudaGetSymbolAddress((void**)&xh, g_xh);
    cudaGetSymbolAddress((void**)&xl, g_xl);
    cudaGetSymbolAddress((void**)&wh, g_wh);
    cudaGetSymbolAddress((void**)&wl, g_wl);
    cudaGetSymbolAddress((void**)&ph, g_ph);
    cudaGetSymbolAddress((void**)&pl, g_pl);
    cudaGetSymbolAddress((void**)&oh, g_oh);
    cudaGetSymbolAddress((void**)&ol, g_ol);

    splith_kernel<<<(2048*49*384/4 + 255)/256, 256>>>(x, xh, xl, 2048*49*384/4);
    splith_kernel<<<(1152*384/4 + 255)/256, 256>>>(qkv_w, wh, wl, 1152*384/4);
    splith_kernel<<<(384*384/4 + 255)/256, 256>>>(proj_w, ph, pl, 384*384/4);

    cpb_kernel<<<169, 512>>>(table, cpb_w1, cpb_b1, cpb_w2);
    gather_kernel<<<(12 * 2401 + 255) / 256, 256>>>(idx);

    // QKV: q,k columns (n 0..767) 3-term; v columns (n 768..1151) 2-term
    gemm_mma<3><<<dim3(784, 6), 512, GEMM_SMEM>>>(xh, xl, wh, wl, 0, 0,
                                                  q_bias, v_bias, nullptr, nullptr);
    gemm_mma<2><<<dim3(784, 3), 512, GEMM_SMEM>>>(xh, xl, wh, wl, 0, 768,
                                                  q_bias, v_bias, nullptr, nullptr);
    attn_kernel<<<2048 * 12, 256>>>(mask, logit_scale);
    gemm_mma<2><<<dim3(784, 3), 512, GEMM_SMEM>>>(oh, ol, ph, pl, 1, 0,
                                                  nullptr, nullptr, proj_b, out);
}

// round 12
// speedup vs baseline: 1.1181x; 1.1181x over previous
#include <cuda_runtime.h>
#include <cuda_fp16.h>
#include <math.h>
#include <stdint.h>

// B=2048 windows, N=49, C=384, H=12, hd=32, nW=64
__device__ float g_q  [2048u*12*49*32];
__device__ float g_k  [2048u*12*49*32];
__device__ float g_v  [2048u*12*49*32];
__device__ __half g_oh[2048u*49*384];   // attn out (fp16), [B][N][C]
__device__ __half g_xh[2048u*49*384];
__device__ __half g_xl[2048u*49*384];   // x residual, x2048
__device__ __half g_wh[1152*384];
__device__ __half g_wl[1152*384];       // w residual, x2048
__device__ __half g_ph[384*384];
__device__ __half g_pl[384*384];        // (unused by 1-term proj; kept for simplicity)
__device__ float g_bt [169*12];
__device__ float g_rpb[12*49*49];

#define LO_SCALE 2048.f
#define LO_INV   (1.f / 2048.f)

// ---------------------------------------------------------------------------
__device__ __forceinline__ uint32_t smem_u32(const void* p) {
    uint32_t a;
    asm("{ .reg .u64 t; cvta.to.shared.u64 t, %1; cvt.u32.u64 %0, t; }" : "=r"(a) : "l"(p));
    return a;
}
__device__ __forceinline__ void cp_async16(uint32_t dst, const void* src) {
    asm volatile("cp.async.cg.shared.global [%0], [%1], 16;" :: "r"(dst), "l"(src));
}
#define CP_COMMIT() asm volatile("cp.async.commit_group;" ::: "memory")
template<int N> __device__ __forceinline__ void cp_wait() {
    asm volatile("cp.async.wait_group %0;" :: "n"(N) : "memory");
}
__device__ __forceinline__ void ldsm4(uint32_t& r0, uint32_t& r1, uint32_t& r2, uint32_t& r3,
                                      uint32_t addr) {
    asm volatile("ldmatrix.sync.aligned.m8n8.x4.shared.b16 {%0,%1,%2,%3}, [%4];"
                 : "=r"(r0), "=r"(r1), "=r"(r2), "=r"(r3) : "r"(addr));
}
__device__ __forceinline__ void mma_f16(float& c0, float& c1, float& c2, float& c3,
                                        uint32_t a0, uint32_t a1, uint32_t a2, uint32_t a3,
                                        uint32_t b0, uint32_t b1) {
    asm volatile("mma.sync.aligned.m16n8k16.row.col.f32.f16.f16.f32 "
                 "{%0,%1,%2,%3}, {%4,%5,%6,%7}, {%8,%9}, {%0,%1,%2,%3};"
                 : "+f"(c0), "+f"(c1), "+f"(c2), "+f"(c3)
                 : "r"(a0), "r"(a1), "r"(a2), "r"(a3), "r"(b0), "r"(b1));
}

// ---------------------------------------------------------------------------
// fp16 hi/lo split: hi = f16(x), lo = f16((x - hi) * 2048)
// ---------------------------------------------------------------------------
__global__ void splith_kernel(const float* __restrict__ in, __half* __restrict__ hi,
                              __half* __restrict__ lo, int n4) {
    int i = blockIdx.x * 256 + threadIdx.x;
    if (i >= n4) return;
    float4 v = ((const float4*)in)[i];
    float vv[4] = {v.x, v.y, v.z, v.w};
    __half h[4], l[4];
    #pragma unroll
    for (int j = 0; j < 4; j++) {
        h[j] = __float2half_rn(vv[j]);
        l[j] = __float2half_rn((vv[j] - __half2float(h[j])) * LO_SCALE);
    }
    ((__half2*)hi)[2*i]   = __half2{h[0], h[1]};
    ((__half2*)hi)[2*i+1] = __half2{h[2], h[3]};
    ((__half2*)lo)[2*i]   = __half2{l[0], l[1]};
    ((__half2*)lo)[2*i+1] = __half2{l[2], l[3]};
}

// ---------------------------------------------------------------------------
// CPB MLP + gather
// ---------------------------------------------------------------------------
__global__ void cpb_kernel(const float* __restrict__ table, const float* __restrict__ w1,
                           const float* __restrict__ b1, const float* __restrict__ w2) {
    __shared__ float red[16];
    int t = blockIdx.x, j = threadIdx.x;
    float t0 = table[t * 2 + 0], t1 = table[t * 2 + 1];
    float h = fmaxf(fmaf(t0, w1[j * 2 + 0], fmaf(t1, w1[j * 2 + 1], b1[j])), 0.f);
    for (int hh = 0; hh < 12; hh++) {
        float v = h * w2[hh * 512 + j];
        #pragma unroll
        for (int o = 16; o > 0; o >>= 1) v += __shfl_down_sync(0xffffffffu, v, o);
        if ((j & 31) == 0) red[j >> 5] = v;
        __syncthreads();
        if (j == 0) {
            float s = 0.f;
            #pragma unroll
            for (int w = 0; w < 16; w++) s += red[w];
            g_bt[t * 12 + hh] = 16.f / (1.f + expf(-s));
        }
        __syncthreads();
    }
}
__global__ void gather_kernel(const int* __restrict__ idx) {
    int e = blockIdx.x * 256 + threadIdx.x;
    if (e >= 12 * 49 * 49) return;
    int h = e / 2401, ij = e - h * 2401;
    g_rpb[e] = g_bt[idx[ij] * 12 + h];
}

// ---------------------------------------------------------------------------
// fp16-limb warp-MMA GEMM, K-chunk 64, 2-stage cp.async, pitch-72 rows.
// TERMS=3: hi*hi + (lo*hi + hi*lo)/2048 (q,k — feeds cosine-attn amplifier)
// TERMS=1: hi*hi only (v, proj — linear error paths, ~3.4e-4)
// 512 thr, 16 warps 4x4, warp tile 32x32, 128x128 block tile.
// ---------------------------------------------------------------------------
#define PITCHE 72                         // fp16 elems per smem row (144B)
#define COMP_B (128 * PITCHE * 2)         // 18432 B per limb tile
#define STAGE_B (4 * COMP_B)              // 73728
#define GEMM_SMEM (2 * STAGE_B)           // 147456

template<int TERMS>
__global__ void __launch_bounds__(512) gemm_mma(
    const __half* __restrict__ Ahi, const __half* __restrict__ Alo,
    const __half* __restrict__ Bhi, const __half* __restrict__ Blo,
    int mode, int n_base,
    const float* __restrict__ bq, const float* __restrict__ bv,
    const float* __restrict__ bp, float* __restrict__ outp)
{
    extern __shared__ char sm[];
    uint32_t sbase = smem_u32(sm);
    int tid = threadIdx.x, wid = tid >> 5, lane = tid & 31;
    int g = lane >> 2, t = lane & 3;
    int grp = lane >> 3, rin = lane & 7;
    int m0 = blockIdx.x * 128, n0 = n_base + blockIdx.y * 128;
    int wm = (wid >> 2) * 32, wn = (wid & 3) * 32;

    float cm[2][4][4], cx[2][4][4];
    #pragma unroll
    for (int mi = 0; mi < 2; mi++)
        #pragma unroll
        for (int nj = 0; nj < 4; nj++)
            #pragma unroll
            for (int r = 0; r < 4; r++) { cm[mi][nj][r] = 0.f; cx[mi][nj][r] = 0.f; }

    // ldmatrix byte offsets within a [128][PITCHE] fp16 tile
    uint32_t abyte[2], bbyte[2];
    #pragma unroll
    for (int mi = 0; mi < 2; mi++)
        abyte[mi] = (uint32_t)((wm + 16 * mi + (grp & 1) * 8 + rin) * (PITCHE * 2)
                               + (grp >> 1) * 16);
    #pragma unroll
    for (int j = 0; j < 2; j++)
        bbyte[j] = (uint32_t)((wn + 16 * j + (grp >> 1) * 8 + rin) * (PITCHE * 2)
                              + (grp & 1) * 16);

    // stage loader: 128 rows x 64 k fp16 per limb
    auto load_stage = [&](int it, int s) {
        int k0 = it * 64;
        uint32_t sb = sbase + s * STAGE_B;
        #pragma unroll
        for (int q = 0; q < 2; q++) {
            int cc = q * 512 + tid;
            int r = cc >> 3, seg = cc & 7;
            uint32_t off = (uint32_t)(r * (PITCHE * 2) + seg * 16);
            size_t ga = (size_t)(m0 + r) * 384 + k0 + seg * 8;
            size_t gb = (size_t)(n0 + r) * 384 + k0 + seg * 8;
            cp_async16(sb + 0 * COMP_B + off, Ahi + ga);
            cp_async16(sb + 2 * COMP_B + off, Bhi + gb);
            if (TERMS >= 2) cp_async16(sb + 1 * COMP_B + off, Alo + ga);
            if (TERMS == 3) cp_async16(sb + 3 * COMP_B + off, Blo + gb);
        }
        CP_COMMIT();
    };

    load_stage(0, 0);
    load_stage(1, 1);

    for (int it = 0; it < 6; ++it) {
        int s = it & 1;
        if (it < 5) cp_wait<1>(); else cp_wait<0>();
        __syncthreads();
        uint32_t sb = sbase + s * STAGE_B;
        #pragma unroll
        for (int kc = 0; kc < 4; kc++) {
            uint32_t kb = (uint32_t)(kc * 32);  // 16 fp16 = 32 bytes per k16
            uint32_t ah[2][4], al[2][4], bh[2][4], bl[2][4];
            #pragma unroll
            for (int mi = 0; mi < 2; mi++) {
                uint32_t ao = sb + abyte[mi] + kb;
                ldsm4(ah[mi][0], ah[mi][1], ah[mi][2], ah[mi][3], ao + 0 * COMP_B);
                if (TERMS >= 2)
                    ldsm4(al[mi][0], al[mi][1], al[mi][2], al[mi][3], ao + 1 * COMP_B);
            }
            #pragma unroll
            for (int j = 0; j < 2; j++) {
                uint32_t bo = sb + bbyte[j] + kb;
                ldsm4(bh[j][0], bh[j][1], bh[j][2], bh[j][3], bo + 2 * COMP_B);
                if (TERMS == 3)
                    ldsm4(bl[j][0], bl[j][1], bl[j][2], bl[j][3], bo + 3 * COMP_B);
            }
            // main term (fp32 accum)
            #pragma unroll
            for (int mi = 0; mi < 2; mi++)
                #pragma unroll
                for (int nj = 0; nj < 4; nj++) {
                    int j = nj >> 1, hf = (nj & 1) * 2;
                    mma_f16(cm[mi][nj][0], cm[mi][nj][1], cm[mi][nj][2], cm[mi][nj][3],
                            ah[mi][0], ah[mi][1], ah[mi][2], ah[mi][3],
                            bh[j][hf], bh[j][hf + 1]);
                }
            if (TERMS >= 2) {
                #pragma unroll
                for (int mi = 0; mi < 2; mi++)
                    #pragma unroll
                    for (int nj = 0; nj < 4; nj++) {
                        int j = nj >> 1, hf = (nj & 1) * 2;
                        mma_f16(cx[mi][nj][0], cx[mi][nj][1], cx[mi][nj][2], cx[mi][nj][3],
                                al[mi][0], al[mi][1], al[mi][2], al[mi][3],
                                bh[j][hf], bh[j][hf + 1]);
                    }
            }
            if (TERMS == 3) {
                #pragma unroll
                for (int mi = 0; mi < 2; mi++)
                    #pragma unroll
                    for (int nj = 0; nj < 4; nj++) {
                        int j = nj >> 1, hf = (nj & 1) * 2;
                        mma_f16(cx[mi][nj][0], cx[mi][nj][1], cx[mi][nj][2], cx[mi][nj][3],
                                ah[mi][0], ah[mi][1], ah[mi][2], ah[mi][3],
                                bl[j][hf], bl[j][hf + 1]);
                    }
            }
        }
        __syncthreads();
        if (it + 2 < 6) load_stage(it + 2, s);
    }

    #pragma unroll
    for (int mi = 0; mi < 2; mi++) {
        #pragma unroll
        for (int half = 0; half < 2; half++) {
            int row = m0 + wm + 16 * mi + g + 8 * half;
            int b = row / 49, nn = row - b * 49;
            #pragma unroll
            for (int nj = 0; nj < 4; nj++) {
                int col = n0 + wn + 8 * nj + 2 * t;
                float2 v;
                if (TERMS >= 2) {
                    v.x = fmaf(cx[mi][nj][2 * half + 0], LO_INV, cm[mi][nj][2 * half + 0]);
                    v.y = fmaf(cx[mi][nj][2 * half + 1], LO_INV, cm[mi][nj][2 * half + 1]);
                } else {
                    v.x = cm[mi][nj][2 * half + 0];
                    v.y = cm[mi][nj][2 * half + 1];
                }
                if (mode == 0) {
                    int which = col / 384;
                    int rem = col - which * 384;
                    int h = rem >> 5, d = rem & 31;
                    if (which == 0)      { v.x += bq[rem]; v.y += bq[rem + 1]; }
                    else if (which == 2) { v.x += bv[rem]; v.y += bv[rem + 1]; }
                    float* dst = ((which == 0) ? g_q : (which == 1) ? g_k : g_v)
                                 + (((size_t)b * 12 + h) * 49 + nn) * 32 + d;
                    *(float2*)dst = v;
                } else {
                    v.x += bp[col]; v.y += bp[col + 1];
                    *(float2*)(outp + (size_t)row * 384 + col) = v;
                }
            }
        }
    }
}

// ---------------------------------------------------------------------------
// Attention (round-6 structure); writes fp16 output for 1-term proj GEMM.
// ---------------------------------------------------------------------------
#define QP 36
#define SP 50

__global__ void __launch_bounds__(256) attn_kernel(const float* __restrict__ mask,
                                                   const float* __restrict__ logit_scale)
{
    __shared__ float sq[49 * QP];
    __shared__ float sk[49 * QP];
    __shared__ float sv[49 * QP];
    __shared__ float sS[49 * SP];
    __shared__ float sredA[245];
    __shared__ float sredB[245];
    int bh = blockIdx.x;
    int b = bh / 12, h = bh - b * 12;
    int tid = threadIdx.x;

    size_t base = (size_t)bh * 49 * 32;
    const float4* gq4 = (const float4*)(g_q + base);
    const float4* gk4 = (const float4*)(g_k + base);
    const float4* gv4 = (const float4*)(g_v + base);
    for (int u = tid; u < 392; u += 256) {
        int r = u >> 3, c4 = (u & 7) * 4;
        *(float4*)(sq + r * QP + c4) = gq4[u];
        *(float4*)(sk + r * QP + c4) = gk4[u];
        *(float4*)(sv + r * QP + c4) = gv4[u];
    }
    __syncthreads();

    if (tid < 98) {
        int r = (tid < 49) ? tid : tid - 49;
        float* s = (tid < 49) ? sq : sk;
        float ss = 0.f;
        #pragma unroll
        for (int d = 0; d < 32; d++) { float x = s[r * QP + d]; ss = fmaf(x, x, ss); }
        float inv = 1.f / fmaxf(sqrtf(ss), 1e-12f);
        if (tid < 49) inv *= expf(fminf(logit_scale[h], 4.60517018598809136804f));
        #pragma unroll
        for (int d = 0; d < 32; d++) s[r * QP + d] *= inv;
    }
    __syncthreads();

    if (tid < 125) {
        int ip = tid / 5, jg = tid - ip * 5;
        int i0 = ip * 2, i1 = i0 + 1;
        bool has1 = (i1 < 49);
        float4 qa[8], qb[8];
        #pragma unroll
        for (int u = 0; u < 8; u++) qa[u] = *(const float4*)(sq + i0 * QP + u * 4);
        if (has1) {
            #pragma unroll
            for (int u = 0; u < 8; u++) qb[u] = *(const float4*)(sq + i1 * QP + u * 4);
        }
        #pragma unroll
        for (int jj = 0; jj < 10; jj++) {
            int j = jg * 10 + jj;
            if (j >= 49) break;
            float a0 = 0.f, a1 = 0.f;
            #pragma unroll
            for (int u = 0; u < 8; u++) {
                float4 kv = *(const float4*)(sk + j * QP + u * 4);
                a0 = fmaf(qa[u].x, kv.x, a0); a0 = fmaf(qa[u].y, kv.y, a0);
                a0 = fmaf(qa[u].z, kv.z, a0); a0 = fmaf(qa[u].w, kv.w, a0);
                if (has1) {
                    a1 = fmaf(qb[u].x, kv.x, a1); a1 = fmaf(qb[u].y, kv.y, a1);
                    a1 = fmaf(qb[u].z, kv.z, a1); a1 = fmaf(qb[u].w, kv.w, a1);
                }
            }
            sS[i0 * SP + j] = a0;
            if (has1) sS[i1 * SP + j] = a1;
        }
    }
    __syncthreads();

    int si = tid / 5, sp = tid - si * 5;
    int j0 = sp * 10, j1 = min(j0 + 10, 49);
    if (tid < 245) {
        const float* rp = g_rpb + (h * 49 + si) * 49;
        const float* mp = mask + ((size_t)(b & 63) * 49 + si) * 49;
        float lmax = -1e30f;
        for (int j = j0; j < j1; j++) {
            float s = sS[si * SP + j] + rp[j] + mp[j];
            sS[si * SP + j] = s;
            lmax = fmaxf(lmax, s);
        }
        sredA[tid] = lmax;
    }
    __syncthreads();
    if (tid < 245) {
        float mx = sredA[si * 5];
        #pragma unroll
        for (int p = 1; p < 5; p++) mx = fmaxf(mx, sredA[si * 5 + p]);
        float lsum = 0.f;
        for (int j = j0; j < j1; j++) {
            float e = expf(sS[si * SP + j] - mx);
            sS[si * SP + j] = e;
            lsum += e;
        }
        sredB[tid] = lsum;
    }
    __syncthreads();
    if (tid < 245) {
        float sum = sredB[si * 5];
        #pragma unroll
        for (int p = 1; p < 5; p++) sum += sredB[si * 5 + p];
        float inv = 1.f / sum;
        for (int j = j0; j < j1; j++) sS[si * SP + j] *= inv;
    }
    __syncthreads();

    if (tid < 104) {
        int ipart = tid >> 3, dq = tid & 7;
        int r0 = ipart * 4;
        float4 acc[4] = {{0,0,0,0},{0,0,0,0},{0,0,0,0},{0,0,0,0}};
        for (int j = 0; j < 49; j++) {
            float4 v = *(const float4*)(sv + j * QP + dq * 4);
            #pragma unroll
            for (int rr = 0; rr < 4; rr++) {
                int r = r0 + rr;
                float s = (r < 49) ? sS[r * SP + j] : 0.f;
                acc[rr].x = fmaf(s, v.x, acc[rr].x);
                acc[rr].y = fmaf(s, v.y, acc[rr].y);
                acc[rr].z = fmaf(s, v.z, acc[rr].z);
                acc[rr].w = fmaf(s, v.w, acc[rr].w);
            }
        }
        #pragma unroll
        for (int rr = 0; rr < 4; rr++) {
            int r = r0 + rr;
            if (r < 49) {
                size_t oidx = ((size_t)b * 49 + r) * 384 + h * 32 + dq * 4;
                __half hh[4];
                hh[0] = __float2half_rn(acc[rr].x);
                hh[1] = __float2half_rn(acc[rr].y);
                hh[2] = __float2half_rn(acc[rr].z);
                hh[3] = __float2half_rn(acc[rr].w);
                *(__half2*)(g_oh + oidx)     = __half2{hh[0], hh[1]};
                *(__half2*)(g_oh + oidx + 2) = __half2{hh[2], hh[3]};
            }
        }
    }
}

// ---------------------------------------------------------------------------
extern "C" void kernel_launch(void* const* d_in, const int* in_sizes, int n_in,
                              void* d_out, int out_size) {
    const float* x           = (const float*)d_in[0];
    const float* mask        = (const float*)d_in[1];
    const float* qkv_w       = (const float*)d_in[2];
    const float* q_bias      = (const float*)d_in[3];
    const float* v_bias      = (const float*)d_in[4];
    const float* logit_scale = (const float*)d_in[5];
    const float* cpb_w1      = (const float*)d_in[6];
    const float* cpb_b1      = (const float*)d_in[7];
    const float* cpb_w2      = (const float*)d_in[8];
    const float* proj_w      = (const float*)d_in[9];
    const float* proj_b      = (const float*)d_in[10];
    const float* table       = (const float*)d_in[11];
    const int*   idx         = (const int*)d_in[12];
    float* out = (float*)d_out;

    cudaFuncSetAttribute(gemm_mma<3>, cudaFuncAttributeMaxDynamicSharedMemorySize, GEMM_SMEM);
    cudaFuncSetAttribute(gemm_mma<1>, cudaFuncAttributeMaxDynamicSharedMemorySize, GEMM_SMEM);

    __half *xh, *xl, *wh, *wl, *ph, *pl, *oh;
    cudaGetSymbolAddress((void**)&xh, g_xh);
    cudaGetSymbolAddress((void**)&xl, g_xl);
    cudaGetSymbolAddress((void**)&wh, g_wh);
    cudaGetSymbolAddress((void**)&wl, g_wl);
    cudaGetSymbolAddress((void**)&ph, g_ph);
    cudaGetSymbolAddress((void**)&pl, g_pl);
    cudaGetSymbolAddress((void**)&oh, g_oh);

    splith_kernel<<<(2048*49*384/4 + 255)/256, 256>>>(x, xh, xl, 2048*49*384/4);
    splith_kernel<<<(1152*384/4 + 255)/256, 256>>>(qkv_w, wh, wl, 1152*384/4);
    splith_kernel<<<(384*384/4 + 255)/256, 256>>>(proj_w, ph, pl, 384*384/4);

    cpb_kernel<<<169, 512>>>(table, cpb_w1, cpb_b1, cpb_w2);
    gather_kernel<<<(12 * 2401 + 255) / 256, 256>>>(idx);

    // QKV: q,k columns (n 0..767) 3-term; v columns (n 768..1151) 1-term
    gemm_mma<3><<<dim3(784, 6), 512, GEMM_SMEM>>>(xh, xl, wh, wl, 0, 0,
                                                  q_bias, v_bias, nullptr, nullptr);
    gemm_mma<1><<<dim3(784, 3), 512, GEMM_SMEM>>>(xh, xl, wh, wl, 0, 768,
                                                  q_bias, v_bias, nullptr, nullptr);
    attn_kernel<<<2048 * 12, 256>>>(mask, logit_scale);
    // proj: 1-term
    gemm_mma<1><<<dim3(784, 3), 512, GEMM_SMEM>>>(oh, nullptr, ph, nullptr, 1, 0,
                                                  nullptr, nullptr, proj_b, out);
}

// round 13
// speedup vs baseline: 1.3074x; 1.1693x over previous
#include <cuda_runtime.h>
#include <cuda_fp16.h>
#include <math.h>
#include <stdint.h>

// B=2048 windows, N=49, C=384, H=12, hd=32, nW=64
__device__ float  g_q [2048u*12*49*32];
__device__ float  g_k [2048u*12*49*32];
__device__ __half g_vh[2048u*12*49*32];  // v in fp16
__device__ __half g_oh[2048u*49*384];    // attn out (fp16), [B][N][C]
__device__ __half g_xh[2048u*49*384];
__device__ __half g_xl[2048u*49*384];    // x residual, x2048
__device__ __half g_wh[1152*384];
__device__ __half g_wl[1152*384];        // w residual, x2048
__device__ __half g_ph[384*384];
__device__ float  g_bt [169*12];
__device__ float  g_rpb[12*49*49];

#define LO_SCALE 2048.f
#define LO_INV   (1.f / 2048.f)

// ---------------------------------------------------------------------------
__device__ __forceinline__ uint32_t smem_u32(const void* p) {
    uint32_t a;
    asm("{ .reg .u64 t; cvta.to.shared.u64 t, %1; cvt.u32.u64 %0, t; }" : "=r"(a) : "l"(p));
    return a;
}
__device__ __forceinline__ void cp_async16(uint32_t dst, const void* src) {
    asm volatile("cp.async.cg.shared.global [%0], [%1], 16;" :: "r"(dst), "l"(src));
}
#define CP_COMMIT() asm volatile("cp.async.commit_group;" ::: "memory")
template<int N> __device__ __forceinline__ void cp_wait() {
    asm volatile("cp.async.wait_group %0;" :: "n"(N) : "memory");
}
__device__ __forceinline__ void ldsm4(uint32_t& r0, uint32_t& r1, uint32_t& r2, uint32_t& r3,
                                      uint32_t addr) {
    asm volatile("ldmatrix.sync.aligned.m8n8.x4.shared.b16 {%0,%1,%2,%3}, [%4];"
                 : "=r"(r0), "=r"(r1), "=r"(r2), "=r"(r3) : "r"(addr));
}
__device__ __forceinline__ void mma_f16(float& c0, float& c1, float& c2, float& c3,
                                        uint32_t a0, uint32_t a1, uint32_t a2, uint32_t a3,
                                        uint32_t b0, uint32_t b1) {
    asm volatile("mma.sync.aligned.m16n8k16.row.col.f32.f16.f16.f32 "
                 "{%0,%1,%2,%3}, {%4,%5,%6,%7}, {%8,%9}, {%0,%1,%2,%3};"
                 : "+f"(c0), "+f"(c1), "+f"(c2), "+f"(c3)
                 : "r"(a0), "r"(a1), "r"(a2), "r"(a3), "r"(b0), "r"(b1));
}

// ---------------------------------------------------------------------------
// fp16 hi/lo split: hi = f16(x), lo = f16((x - hi) * 2048)
// ---------------------------------------------------------------------------
__global__ void splith_kernel(const float* __restrict__ in, __half* __restrict__ hi,
                              __half* __restrict__ lo, int n4) {
    int i = blockIdx.x * 256 + threadIdx.x;
    if (i >= n4) return;
    float4 v = ((const float4*)in)[i];
    float vv[4] = {v.x, v.y, v.z, v.w};
    __half h[4], l[4];
    #pragma unroll
    for (int j = 0; j < 4; j++) {
        h[j] = __float2half_rn(vv[j]);
        if (lo) l[j] = __float2half_rn((vv[j] - __half2float(h[j])) * LO_SCALE);
    }
    ((__half2*)hi)[2*i]   = __half2{h[0], h[1]};
    ((__half2*)hi)[2*i+1] = __half2{h[2], h[3]};
    if (lo) {
        ((__half2*)lo)[2*i]   = __half2{l[0], l[1]};
        ((__half2*)lo)[2*i+1] = __half2{l[2], l[3]};
    }
}

// ---------------------------------------------------------------------------
// CPB MLP + gather
// ---------------------------------------------------------------------------
__global__ void cpb_kernel(const float* __restrict__ table, const float* __restrict__ w1,
                           const float* __restrict__ b1, const float* __restrict__ w2) {
    __shared__ float red[16];
    int t = blockIdx.x, j = threadIdx.x;
    float t0 = table[t * 2 + 0], t1 = table[t * 2 + 1];
    float h = fmaxf(fmaf(t0, w1[j * 2 + 0], fmaf(t1, w1[j * 2 + 1], b1[j])), 0.f);
    for (int hh = 0; hh < 12; hh++) {
        float v = h * w2[hh * 512 + j];
        #pragma unroll
        for (int o = 16; o > 0; o >>= 1) v += __shfl_down_sync(0xffffffffu, v, o);
        if ((j & 31) == 0) red[j >> 5] = v;
        __syncthreads();
        if (j == 0) {
            float s = 0.f;
            #pragma unroll
            for (int w = 0; w < 16; w++) s += red[w];
            g_bt[t * 12 + hh] = 16.f / (1.f + expf(-s));
        }
        __syncthreads();
    }
}
__global__ void gather_kernel(const int* __restrict__ idx) {
    int e = blockIdx.x * 256 + threadIdx.x;
    if (e >= 12 * 49 * 49) return;
    int h = e / 2401, ij = e - h * 2401;
    g_rpb[e] = g_bt[idx[ij] * 12 + h];
}

// ---------------------------------------------------------------------------
// fp16-limb warp-MMA GEMM, K-chunk 64, 3-stage single-sync cp.async pipeline.
// TERMS=3: hi*hi + (lo*hi + hi*lo)/2048 (q,k). TERMS=1: hi*hi (v fp16, proj).
// 512 thr, 16 warps 4x4, warp tile 32x32, 128x128 block tile, pitch-72 rows.
// ---------------------------------------------------------------------------
#define PITCHE 72
#define COMP_B (128 * PITCHE * 2)          // 18432 B per limb tile
#define GEMM_SMEM3 (3 * 4 * COMP_B)        // 221184
#define GEMM_SMEM1 (3 * 2 * COMP_B)        // 110592

template<int TERMS>
__global__ void __launch_bounds__(512) gemm_mma(
    const __half* __restrict__ Ahi, const __half* __restrict__ Alo,
    const __half* __restrict__ Bhi, const __half* __restrict__ Blo,
    int mode, int n_base,
    const float* __restrict__ bq, const float* __restrict__ bv,
    const float* __restrict__ bp, float* __restrict__ outp)
{
    constexpr int NCOMP = (TERMS == 3) ? 4 : 2;
    constexpr int C_AHI = 0;
    constexpr int C_ALO = 1;
    constexpr int C_BHI = (TERMS == 3) ? 2 : 1;
    constexpr int C_BLO = 3;
    constexpr uint32_t STAGE_B = NCOMP * COMP_B;

    extern __shared__ char sm[];
    uint32_t sbase = smem_u32(sm);
    int tid = threadIdx.x, wid = tid >> 5, lane = tid & 31;
    int g = lane >> 2, t = lane & 3;
    int grp = lane >> 3, rin = lane & 7;
    int m0 = blockIdx.x * 128, n0 = n_base + blockIdx.y * 128;
    int wm = (wid >> 2) * 32, wn = (wid & 3) * 32;

    float cm[2][4][4], cx[2][4][4];
    #pragma unroll
    for (int mi = 0; mi < 2; mi++)
        #pragma unroll
        for (int nj = 0; nj < 4; nj++)
            #pragma unroll
            for (int r = 0; r < 4; r++) { cm[mi][nj][r] = 0.f; cx[mi][nj][r] = 0.f; }

    uint32_t abyte[2], bbyte[2];
    #pragma unroll
    for (int mi = 0; mi < 2; mi++)
        abyte[mi] = (uint32_t)((wm + 16 * mi + (grp & 1) * 8 + rin) * (PITCHE * 2)
                               + (grp >> 1) * 16);
    #pragma unroll
    for (int j = 0; j < 2; j++)
        bbyte[j] = (uint32_t)((wn + 16 * j + (grp >> 1) * 8 + rin) * (PITCHE * 2)
                              + (grp & 1) * 16);

    auto load_stage = [&](int it, int s) {
        int k0 = it * 64;
        uint32_t sb = sbase + (uint32_t)s * STAGE_B;
        #pragma unroll
        for (int q = 0; q < 2; q++) {
            int cc = q * 512 + tid;
            int r = cc >> 3, seg = cc & 7;
            uint32_t off = (uint32_t)(r * (PITCHE * 2) + seg * 16);
            size_t ga = (size_t)(m0 + r) * 384 + k0 + seg * 8;
            size_t gb = (size_t)(n0 + r) * 384 + k0 + seg * 8;
            cp_async16(sb + C_AHI * COMP_B + off, Ahi + ga);
            cp_async16(sb + C_BHI * COMP_B + off, Bhi + gb);
            if (TERMS == 3) {
                cp_async16(sb + C_ALO * COMP_B + off, Alo + ga);
                cp_async16(sb + C_BLO * COMP_B + off, Blo + gb);
            }
        }
        CP_COMMIT();
    };

    load_stage(0, 0);
    load_stage(1, 1);

    for (int it = 0; it < 6; ++it) {
        int s = it % 3;
        if (it < 5) cp_wait<1>(); else cp_wait<0>();
        __syncthreads();   // stage s ready; all warps finished iter it-1 -> slot (it+2)%3 free
        if (it + 2 < 6) load_stage(it + 2, (it + 2) % 3);
        uint32_t sb = sbase + (uint32_t)s * STAGE_B;
        #pragma unroll
        for (int kc = 0; kc < 4; kc++) {
            uint32_t kb = (uint32_t)(kc * 32);
            uint32_t ah[2][4], al[2][4], bh[2][4], bl[2][4];
            #pragma unroll
            for (int mi = 0; mi < 2; mi++) {
                uint32_t ao = sb + abyte[mi] + kb;
                ldsm4(ah[mi][0], ah[mi][1], ah[mi][2], ah[mi][3], ao + C_AHI * COMP_B);
                if (TERMS == 3)
                    ldsm4(al[mi][0], al[mi][1], al[mi][2], al[mi][3], ao + C_ALO * COMP_B);
            }
            #pragma unroll
            for (int j = 0; j < 2; j++) {
                uint32_t bo = sb + bbyte[j] + kb;
                ldsm4(bh[j][0], bh[j][1], bh[j][2], bh[j][3], bo + C_BHI * COMP_B);
                if (TERMS == 3)
                    ldsm4(bl[j][0], bl[j][1], bl[j][2], bl[j][3], bo + C_BLO * COMP_B);
            }
            #pragma unroll
            for (int mi = 0; mi < 2; mi++)
                #pragma unroll
                for (int nj = 0; nj < 4; nj++) {
                    int j = nj >> 1, hf = (nj & 1) * 2;
                    mma_f16(cm[mi][nj][0], cm[mi][nj][1], cm[mi][nj][2], cm[mi][nj][3],
                            ah[mi][0], ah[mi][1], ah[mi][2], ah[mi][3],
                            bh[j][hf], bh[j][hf + 1]);
                }
            if (TERMS == 3) {
                #pragma unroll
                for (int mi = 0; mi < 2; mi++)
                    #pragma unroll
                    for (int nj = 0; nj < 4; nj++) {
                        int j = nj >> 1, hf = (nj & 1) * 2;
                        mma_f16(cx[mi][nj][0], cx[mi][nj][1], cx[mi][nj][2], cx[mi][nj][3],
                                al[mi][0], al[mi][1], al[mi][2], al[mi][3],
                                bh[j][hf], bh[j][hf + 1]);
                    }
                #pragma unroll
                for (int mi = 0; mi < 2; mi++)
                    #pragma unroll
                    for (int nj = 0; nj < 4; nj++) {
                        int j = nj >> 1, hf = (nj & 1) * 2;
                        mma_f16(cx[mi][nj][0], cx[mi][nj][1], cx[mi][nj][2], cx[mi][nj][3],
                                ah[mi][0], ah[mi][1], ah[mi][2], ah[mi][3],
                                bl[j][hf], bl[j][hf + 1]);
                    }
            }
        }
    }

    #pragma unroll
    for (int mi = 0; mi < 2; mi++) {
        #pragma unroll
        for (int half = 0; half < 2; half++) {
            int row = m0 + wm + 16 * mi + g + 8 * half;
            int b = row / 49, nn = row - b * 49;
            #pragma unroll
            for (int nj = 0; nj < 4; nj++) {
                int col = n0 + wn + 8 * nj + 2 * t;
                float2 v;
                if (TERMS == 3) {
                    v.x = fmaf(cx[mi][nj][2 * half + 0], LO_INV, cm[mi][nj][2 * half + 0]);
                    v.y = fmaf(cx[mi][nj][2 * half + 1], LO_INV, cm[mi][nj][2 * half + 1]);
                } else {
                    v.x = cm[mi][nj][2 * half + 0];
                    v.y = cm[mi][nj][2 * half + 1];
                }
                if (mode == 0) {
                    int which = col / 384;
                    int rem = col - which * 384;
                    int h = rem >> 5, d = rem & 31;
                    if (TERMS == 3) {
                        // q or k columns (fp32 out)
                        if (which == 0) { v.x += bq[rem]; v.y += bq[rem + 1]; }
                        float* dst = ((which == 0) ? g_q : g_k)
                                     + (((size_t)b * 12 + h) * 49 + nn) * 32 + d;
                        *(float2*)dst = v;
                    } else {
                        // v columns (fp16 out)
                        v.x += bv[rem]; v.y += bv[rem + 1];
                        __half* dst = g_vh + (((size_t)b * 12 + h) * 49 + nn) * 32 + d;
                        *(__half2*)dst = __half2{__float2half_rn(v.x), __float2half_rn(v.y)};
                    }
                } else {
                    v.x += bp[col]; v.y += bp[col + 1];
                    *(float2*)(outp + (size_t)row * 384 + col) = v;
                }
            }
        }
    }
}

// ---------------------------------------------------------------------------
// Attention v3: pitch-36 smem, 245-thr S phase, 200-thr PV, fp16 v input.
// ---------------------------------------------------------------------------
#define QP 36
#define SP 50

__global__ void __launch_bounds__(256) attn_kernel(const float* __restrict__ mask,
                                                   const float* __restrict__ logit_scale)
{
    __shared__ float sq[49 * QP];
    __shared__ float sk[49 * QP];
    __shared__ float sv[49 * QP];
    __shared__ float sS[49 * SP];
    __shared__ float sredA[245];
    __shared__ float sredB[245];
    int bh = blockIdx.x;
    int b = bh / 12, h = bh - b * 12;
    int tid = threadIdx.x;

    size_t base = (size_t)bh * 49 * 32;
    const float4* gq4 = (const float4*)(g_q + base);
    const float4* gk4 = (const float4*)(g_k + base);
    for (int u = tid; u < 784; u += 256) {
        if (u < 392) {
            int r = u >> 3, c4 = (u & 7) * 4;
            *(float4*)(sq + r * QP + c4) = gq4[u];
        } else {
            int w = u - 392;
            int r = w >> 3, c4 = (w & 7) * 4;
            *(float4*)(sk + r * QP + c4) = gk4[w];
        }
    }
    // v: fp16 -> fp32 smem. 196 uint4 = 8 halves each.
    if (tid < 196) {
        int r = tid >> 2, c8 = (tid & 3) * 8;
        uint4 pv = *(const uint4*)(g_vh + base + r * 32 + c8);
        float2 f0 = __half22float2(*(__half2*)&pv.x);
        float2 f1 = __half22float2(*(__half2*)&pv.y);
        float2 f2 = __half22float2(*(__half2*)&pv.z);
        float2 f3 = __half22float2(*(__half2*)&pv.w);
        float* d = sv + r * QP + c8;
        d[0] = f0.x; d[1] = f0.y; d[2] = f1.x; d[3] = f1.y;
        d[4] = f2.x; d[5] = f2.y; d[6] = f3.x; d[7] = f3.y;
    }
    __syncthreads();

    if (tid < 98) {
        int r = (tid < 49) ? tid : tid - 49;
        float* s = (tid < 49) ? sq : sk;
        float ss = 0.f;
        #pragma unroll
        for (int d = 0; d < 32; d++) { float x = s[r * QP + d]; ss = fmaf(x, x, ss); }
        float inv = 1.f / fmaxf(sqrtf(ss), 1e-12f);
        if (tid < 49) inv *= expf(fminf(logit_scale[h], 4.60517018598809136804f));
        #pragma unroll
        for (int d = 0; d < 32; d++) s[r * QP + d] *= inv;
    }
    __syncthreads();

    // S = qn @ kn^T : 245 threads, 1 row x <=10 cols, q row in regs.
    int si = tid / 5, sp = tid - si * 5;
    int j0 = sp * 10, j1 = min(j0 + 10, 49);
    if (tid < 245) {
        float4 qr[8];
        #pragma unroll
        for (int u = 0; u < 8; u++) qr[u] = *(const float4*)(sq + si * QP + u * 4);
        for (int j = j0; j < j1; j++) {
            float a0 = 0.f;
            #pragma unroll
            for (int u = 0; u < 8; u++) {
                float4 kv = *(const float4*)(sk + j * QP + u * 4);
                a0 = fmaf(qr[u].x, kv.x, a0); a0 = fmaf(qr[u].y, kv.y, a0);
                a0 = fmaf(qr[u].z, kv.z, a0); a0 = fmaf(qr[u].w, kv.w, a0);
            }
            sS[si * SP + j] = a0;
        }
    }
    __syncthreads();

    // softmax: 245 threads, two-stage reductions
    if (tid < 245) {
        const float* rp = g_rpb + (h * 49 + si) * 49;
        const float* mp = mask + ((size_t)(b & 63) * 49 + si) * 49;
        float lmax = -1e30f;
        for (int j = j0; j < j1; j++) {
            float s = sS[si * SP + j] + rp[j] + mp[j];
            sS[si * SP + j] = s;
            lmax = fmaxf(lmax, s);
        }
        sredA[tid] = lmax;
    }
    __syncthreads();
    if (tid < 245) {
        float mx = sredA[si * 5];
        #pragma unroll
        for (int p = 1; p < 5; p++) mx = fmaxf(mx, sredA[si * 5 + p]);
        float lsum = 0.f;
        for (int j = j0; j < j1; j++) {
            float e = expf(sS[si * SP + j] - mx);
            sS[si * SP + j] = e;
            lsum += e;
        }
        sredB[tid] = lsum;
    }
    __syncthreads();
    if (tid < 245) {
        float sum = sredB[si * 5];
        #pragma unroll
        for (int p = 1; p < 5; p++) sum += sredB[si * 5 + p];
        float inv = 1.f / sum;
        for (int j = j0; j < j1; j++) sS[si * SP + j] *= inv;
    }
    __syncthreads();

    // PV: 200 threads, 2 rows x 4 cols; out = P @ V -> g_oh fp16
    if (tid < 200) {
        int ipart = tid >> 3, dq = tid & 7;
        int r0 = ipart * 2;
        bool has1 = (r0 + 1 < 49);
        float4 a0 = {0, 0, 0, 0}, a1 = {0, 0, 0, 0};
        for (int j = 0; j < 49; j++) {
            float4 v = *(const float4*)(sv + j * QP + dq * 4);
            float s0 = sS[r0 * SP + j];
            a0.x = fmaf(s0, v.x, a0.x); a0.y = fmaf(s0, v.y, a0.y);
            a0.z = fmaf(s0, v.z, a0.z); a0.w = fmaf(s0, v.w, a0.w);
            if (has1) {
                float s1 = sS[(r0 + 1) * SP + j];
                a1.x = fmaf(s1, v.x, a1.x); a1.y = fmaf(s1, v.y, a1.y);
                a1.z = fmaf(s1, v.z, a1.z); a1.w = fmaf(s1, v.w, a1.w);
            }
        }
        size_t o0 = ((size_t)b * 49 + r0) * 384 + h * 32 + dq * 4;
        *(__half2*)(g_oh + o0)     = __half2{__float2half_rn(a0.x), __float2half_rn(a0.y)};
        *(__half2*)(g_oh + o0 + 2) = __half2{__float2half_rn(a0.z), __float2half_rn(a0.w)};
        if (has1) {
            size_t o1 = o0 + 384;
            *(__half2*)(g_oh + o1)     = __half2{__float2half_rn(a1.x), __float2half_rn(a1.y)};
            *(__half2*)(g_oh + o1 + 2) = __half2{__float2half_rn(a1.z), __float2half_rn(a1.w)};
        }
    }
}

// ---------------------------------------------------------------------------
extern "C" void kernel_launch(void* const* d_in, const int* in_sizes, int n_in,
                              void* d_out, int out_size) {
    const float* x           = (const float*)d_in[0];
    const float* mask        = (const float*)d_in[1];
    const float* qkv_w       = (const float*)d_in[2];
    const float* q_bias      = (const float*)d_in[3];
    const float* v_bias      = (const float*)d_in[4];
    const float* logit_scale = (const float*)d_in[5];
    const float* cpb_w1      = (const float*)d_in[6];
    const float* cpb_b1      = (const float*)d_in[7];
    const float* cpb_w2      = (const float*)d_in[8];
    const float* proj_w      = (const float*)d_in[9];
    const float* proj_b      = (const float*)d_in[10];
    const float* table       = (const float*)d_in[11];
    const int*   idx         = (const int*)d_in[12];
    float* out = (float*)d_out;

    cudaFuncSetAttribute(gemm_mma<3>, cudaFuncAttributeMaxDynamicSharedMemorySize, GEMM_SMEM3);
    cudaFuncSetAttribute(gemm_mma<1>, cudaFuncAttributeMaxDynamicSharedMemorySize, GEMM_SMEM1);

    __half *xh, *xl, *wh, *wl, *ph, *oh;
    cudaGetSymbolAddress((void**)&xh, g_xh);
    cudaGetSymbolAddress((void**)&xl, g_xl);
    cudaGetSymbolAddress((void**)&wh, g_wh);
    cudaGetSymbolAddress((void**)&wl, g_wl);
    cudaGetSymbolAddress((void**)&ph, g_ph);
    cudaGetSymbolAddress((void**)&oh, g_oh);

    splith_kernel<<<(2048*49*384/4 + 255)/256, 256>>>(x, xh, xl, 2048*49*384/4);
    splith_kernel<<<(1152*384/4 + 255)/256, 256>>>(qkv_w, wh, wl, 1152*384/4);
    splith_kernel<<<(384*384/4 + 255)/256, 256>>>(proj_w, ph, nullptr, 384*384/4);

    cpb_kernel<<<169, 512>>>(table, cpb_w1, cpb_b1, cpb_w2);
    gather_kernel<<<(12 * 2401 + 255) / 256, 256>>>(idx);

    // QKV: q,k columns (n 0..767) 3-term; v columns (n 768..1151) 1-term (fp16 out)
    gemm_mma<3><<<dim3(784, 6), 512, GEMM_SMEM3>>>(xh, xl, wh, wl, 0, 0,
                                                   q_bias, v_bias, nullptr, nullptr);
    gemm_mma<1><<<dim3(784, 3), 512, GEMM_SMEM1>>>(xh, nullptr, wh, nullptr, 0, 768,
                                                   q_bias, v_bias, nullptr, nullptr);
    attn_kernel<<<2048 * 12, 256>>>(mask, logit_scale);
    gemm_mma<1><<<dim3(784, 3), 512, GEMM_SMEM1>>>(oh, nullptr, ph, nullptr, 1, 0,
                                                   nullptr, nullptr, proj_b, out);
}